// round 1
// baseline (speedup 1.0000x reference)
#include <cuda_runtime.h>
#include <math.h>

#define Tt   1024
#define Bb   4
#define Dd   1024
#define Hh   16
#define DH   64
#define FFd  4096
#define NR   (Tt*Bb)      // 4096 rows
#define LDR  (Bb*Dd)      // 4096: stride between consecutive t for fixed b
#define NLAYER 4

// ---------------- scratch (device globals: no allocation allowed) ----------
__device__ float g_X[NR*Dd];
__device__ float g_Z[NR*Dd];
__device__ float g_Hb[NR*FFd];          // FF hidden 64 MB
__device__ float g_F[NR*Dd];
__device__ float g_Kb[NR*Dd];
__device__ float g_Qb[NR*Dd];
__device__ float g_Vb[NR*Dd];
__device__ float g_S[64*1024*1024];     // scores (B*H, T, T) 256 MB
__device__ float g_O[NR*Dd];

// ---------------- generic SGEMM: C = [relu](A @ W + bias) ------------------
// A: [M,K] row-major, W: [K,N] row-major, C: [M,N]. M%128==0, N%128==0, K%8==0.
template<bool RELU>
__global__ __launch_bounds__(256)
void gemm_kernel(const float* __restrict__ A, const float* __restrict__ W,
                 const float* __restrict__ bias, float* __restrict__ C,
                 int M, int N, int K) {
    const int BM = 128, BN = 128, BK = 8, TM = 8, TN = 8;
    __shared__ float As[BK][BM];
    __shared__ float Bs[BK][BN];

    int tid = threadIdx.x;
    int bm = blockIdx.y * BM;
    int bn = blockIdx.x * BN;
    int tRow = (tid / 16) * TM;
    int tCol = (tid % 16) * TN;

    int aRow = tid >> 1;          // 0..127
    int aCol = (tid & 1) * 4;     // 0 or 4
    int bRow = tid >> 5;          // 0..7
    int bCol = (tid & 31) * 4;    // 0..124

    const float* Ag = A + (size_t)bm * K;
    const float* Wg = W + bn;

    float acc[TM][TN];
    #pragma unroll
    for (int i = 0; i < TM; i++)
        #pragma unroll
        for (int j = 0; j < TN; j++) acc[i][j] = 0.f;

    for (int k0 = 0; k0 < K; k0 += BK) {
        float4 av = *(const float4*)(Ag + (size_t)aRow * K + k0 + aCol);
        As[aCol+0][aRow] = av.x;
        As[aCol+1][aRow] = av.y;
        As[aCol+2][aRow] = av.z;
        As[aCol+3][aRow] = av.w;
        float4 bv = *(const float4*)(Wg + (size_t)(k0 + bRow) * N + bCol);
        *(float4*)&Bs[bRow][bCol] = bv;
        __syncthreads();

        #pragma unroll
        for (int kk = 0; kk < BK; kk++) {
            float ra[TM], rb[TN];
            #pragma unroll
            for (int i = 0; i < TM; i++) ra[i] = As[kk][tRow + i];
            #pragma unroll
            for (int j = 0; j < TN; j++) rb[j] = Bs[kk][tCol + j];
            #pragma unroll
            for (int i = 0; i < TM; i++)
                #pragma unroll
                for (int j = 0; j < TN; j++)
                    acc[i][j] += ra[i] * rb[j];
        }
        __syncthreads();
    }

    #pragma unroll
    for (int i = 0; i < TM; i++) {
        #pragma unroll
        for (int j = 0; j < TN; j += 4) {
            float4 o;
            o.x = acc[i][j+0] + bias[bn + tCol + j + 0];
            o.y = acc[i][j+1] + bias[bn + tCol + j + 1];
            o.z = acc[i][j+2] + bias[bn + tCol + j + 2];
            o.w = acc[i][j+3] + bias[bn + tCol + j + 3];
            if (RELU) {
                o.x = fmaxf(o.x, 0.f); o.y = fmaxf(o.y, 0.f);
                o.z = fmaxf(o.z, 0.f); o.w = fmaxf(o.w, 0.f);
            }
            *(float4*)(C + (size_t)(bm + tRow + i) * N + bn + tCol + j) = o;
        }
    }
}

// ------------- batched scores: S[bh][i][j] = (K_i . Q_j) / 32 --------------
// K,Q stored [T*B, H*64] (row = t*B+b). Per (b,h): element [i][d] at
// base + i*LDR + d with base = b*Dd + h*DH.
__global__ __launch_bounds__(256)
void scores_kernel(const float* __restrict__ Km, const float* __restrict__ Qm,
                   float* __restrict__ S) {
    __shared__ float Ks[64][65];
    __shared__ float Qs[64][65];

    int bh = blockIdx.z;
    int b = bh / Hh, h = bh % Hh;
    int base = b * Dd + h * DH;
    int i0 = blockIdx.y * 64;
    int j0 = blockIdx.x * 64;
    int tid = threadIdx.x;

    int r  = tid >> 4;          // 0..15
    int c4 = (tid & 15) * 4;    // 0..60

    const float* Kp = Km + base;
    const float* Qp = Qm + base;
    #pragma unroll
    for (int rr = r; rr < 64; rr += 16) {
        float4 kv = *(const float4*)(Kp + (size_t)(i0 + rr) * LDR + c4);
        Ks[rr][c4+0] = kv.x; Ks[rr][c4+1] = kv.y;
        Ks[rr][c4+2] = kv.z; Ks[rr][c4+3] = kv.w;
        float4 qv = *(const float4*)(Qp + (size_t)(j0 + rr) * LDR + c4);
        Qs[rr][c4+0] = qv.x; Qs[rr][c4+1] = qv.y;
        Qs[rr][c4+2] = qv.z; Qs[rr][c4+3] = qv.w;
    }
    __syncthreads();

    int tRow = (tid / 16) * 4;
    int tCol = (tid % 16) * 4;
    float acc[4][4];
    #pragma unroll
    for (int i = 0; i < 4; i++)
        #pragma unroll
        for (int j = 0; j < 4; j++) acc[i][j] = 0.f;

    #pragma unroll 8
    for (int d = 0; d < 64; d++) {
        float rk[4], rq[4];
        #pragma unroll
        for (int i = 0; i < 4; i++) rk[i] = Ks[tRow + i][d];
        #pragma unroll
        for (int j = 0; j < 4; j++) rq[j] = Qs[tCol + j][d];
        #pragma unroll
        for (int i = 0; i < 4; i++)
            #pragma unroll
            for (int j = 0; j < 4; j++)
                acc[i][j] += rk[i] * rq[j];
    }

    float* Sp = S + (size_t)bh * Tt * Tt;
    const float scale = 0.03125f;   // 1/sqrt(D) = 1/32
    #pragma unroll
    for (int i = 0; i < 4; i++) {
        float4 o;
        o.x = acc[i][0] * scale; o.y = acc[i][1] * scale;
        o.z = acc[i][2] * scale; o.w = acc[i][3] * scale;
        *(float4*)(Sp + (size_t)(i0 + tRow + i) * Tt + j0 + tCol) = o;
    }
}

// ------------- in-place row softmax over last axis (rows of 1024) ----------
__global__ __launch_bounds__(256)
void softmax_kernel(float* __restrict__ S) {
    size_t row = blockIdx.x;
    float* p = S + row * Tt;
    int tid = threadIdx.x;

    float4 v = ((float4*)p)[tid];
    float m = fmaxf(fmaxf(v.x, v.y), fmaxf(v.z, v.w));
    #pragma unroll
    for (int o = 16; o > 0; o >>= 1) m = fmaxf(m, __shfl_xor_sync(0xffffffffu, m, o));

    __shared__ float sm[8];
    __shared__ float bmax, bsuminv;
    if ((tid & 31) == 0) sm[tid >> 5] = m;
    __syncthreads();
    if (tid == 0) {
        float mm = sm[0];
        #pragma unroll
        for (int i = 1; i < 8; i++) mm = fmaxf(mm, sm[i]);
        bmax = mm;
    }
    __syncthreads();
    m = bmax;

    v.x = expf(v.x - m); v.y = expf(v.y - m);
    v.z = expf(v.z - m); v.w = expf(v.w - m);
    float s = v.x + v.y + v.z + v.w;
    #pragma unroll
    for (int o = 16; o > 0; o >>= 1) s += __shfl_xor_sync(0xffffffffu, s, o);
    if ((tid & 31) == 0) sm[tid >> 5] = s;
    __syncthreads();
    if (tid == 0) {
        float t = 0.f;
        #pragma unroll
        for (int i = 0; i < 8; i++) t += sm[i];
        bsuminv = 1.f / t;
    }
    __syncthreads();
    float inv = bsuminv;
    v.x *= inv; v.y *= inv; v.z *= inv; v.w *= inv;
    ((float4*)p)[tid] = v;
}

// ------------- attn out: O[bh][i][:] = sum_j A[i][j] * V[j][:] -------------
__global__ __launch_bounds__(256)
void attnout_kernel(const float* __restrict__ S, const float* __restrict__ Vm,
                    float* __restrict__ O) {
    __shared__ float As[64][33];
    __shared__ float Vs[32][64];

    int bh = blockIdx.z;
    int b = bh / Hh, h = bh % Hh;
    int base = b * Dd + h * DH;
    int i0 = blockIdx.y * 64;
    int tid = threadIdx.x;

    const float* Sp = S + (size_t)bh * Tt * Tt;
    const float* Vp = Vm + base;

    int tRow = (tid / 16) * 4;
    int tCol = (tid % 16) * 4;
    float acc[4][4];
    #pragma unroll
    for (int i = 0; i < 4; i++)
        #pragma unroll
        for (int j = 0; j < 4; j++) acc[i][j] = 0.f;

    for (int k0 = 0; k0 < Tt; k0 += 32) {
        // load A tile 64x32 (512 float4, 2 per thread)
        #pragma unroll
        for (int p = 0; p < 2; p++) {
            int lin = tid + p * 256;
            int ar = lin >> 3;            // 0..63
            int ac = (lin & 7) * 4;       // 0..28
            float4 av = *(const float4*)(Sp + (size_t)(i0 + ar) * Tt + k0 + ac);
            As[ar][ac+0] = av.x; As[ar][ac+1] = av.y;
            As[ar][ac+2] = av.z; As[ar][ac+3] = av.w;
        }
        // load V tile 32x64 (512 float4, 2 per thread)
        #pragma unroll
        for (int p = 0; p < 2; p++) {
            int lin = tid + p * 256;
            int vr = lin >> 4;            // 0..31
            int vc = (lin & 15) * 4;      // 0..60
            float4 vv = *(const float4*)(Vp + (size_t)(k0 + vr) * LDR + vc);
            *(float4*)&Vs[vr][vc] = vv;
        }
        __syncthreads();

        #pragma unroll 8
        for (int kk = 0; kk < 32; kk++) {
            float ra[4], rb[4];
            #pragma unroll
            for (int i = 0; i < 4; i++) ra[i] = As[tRow + i][kk];
            #pragma unroll
            for (int j = 0; j < 4; j++) rb[j] = Vs[kk][tCol + j];
            #pragma unroll
            for (int i = 0; i < 4; i++)
                #pragma unroll
                for (int j = 0; j < 4; j++)
                    acc[i][j] += ra[i] * rb[j];
        }
        __syncthreads();
    }

    float* Op = O + base;
    #pragma unroll
    for (int i = 0; i < 4; i++) {
        float4 o;
        o.x = acc[i][0]; o.y = acc[i][1]; o.z = acc[i][2]; o.w = acc[i][3];
        *(float4*)(Op + (size_t)(i0 + tRow + i) * LDR + tCol) = o;
    }
}

// ------------- resnorm: out = ((x+fx) - mean) / (std_ddof1 + eps) ----------
__global__ __launch_bounds__(256)
void resnorm_kernel(const float* __restrict__ X, const float* __restrict__ Fx,
                    float* __restrict__ Out) {
    int row = blockIdx.x;
    const float4* xp = (const float4*)(X + (size_t)row * Dd);
    const float4* fp = (const float4*)(Fx + (size_t)row * Dd);
    float4* op = (float4*)(Out + (size_t)row * Dd);
    int tid = threadIdx.x;

    float4 x = xp[tid], f = fp[tid];
    float4 y;
    y.x = x.x + f.x; y.y = x.y + f.y; y.z = x.z + f.z; y.w = x.w + f.w;

    float s  = y.x + y.y + y.z + y.w;
    float ss = y.x*y.x + y.y*y.y + y.z*y.z + y.w*y.w;
    #pragma unroll
    for (int o = 16; o > 0; o >>= 1) {
        s  += __shfl_xor_sync(0xffffffffu, s, o);
        ss += __shfl_xor_sync(0xffffffffu, ss, o);
    }
    __shared__ float sh1[8], sh2[8];
    __shared__ float bmu, binv;
    if ((tid & 31) == 0) { sh1[tid >> 5] = s; sh2[tid >> 5] = ss; }
    __syncthreads();
    if (tid == 0) {
        float ts = 0.f, tss = 0.f;
        #pragma unroll
        for (int i = 0; i < 8; i++) { ts += sh1[i]; tss += sh2[i]; }
        float mu  = ts * (1.f / 1024.f);
        float var = (tss - 1024.f * mu * mu) * (1.f / 1023.f);
        float sd  = sqrtf(fmaxf(var, 0.f));
        bmu = mu;
        binv = 1.f / (sd + 1e-6f);
    }
    __syncthreads();
    float mu = bmu, inv = binv;
    float4 o;
    o.x = (y.x - mu) * inv; o.y = (y.y - mu) * inv;
    o.z = (y.z - mu) * inv; o.w = (y.w - mu) * inv;
    op[tid] = o;
}

// ------------- trivial copy ------------------------------------------------
__global__ void copy_kernel(const float* __restrict__ src, float* __restrict__ dst, int n) {
    int i = blockIdx.x * blockDim.x + threadIdx.x;
    if (i < n) dst[i] = src[i];
}

// ---------------------------------------------------------------------------
extern "C" void kernel_launch(void* const* d_in, const int* in_sizes, int n_in,
                              void* d_out, int out_size) {
    const float* x  = (const float*)d_in[0];
    // d_in[1] = mask: all-True in this problem -> ignored
    const float* Wk = (const float*)d_in[2];
    const float* bk = (const float*)d_in[3];
    const float* Wq = (const float*)d_in[4];
    const float* bq = (const float*)d_in[5];
    const float* Wv = (const float*)d_in[6];
    const float* bv = (const float*)d_in[7];
    const float* W1 = (const float*)d_in[8];
    const float* b1 = (const float*)d_in[9];
    const float* W2 = (const float*)d_in[10];
    const float* b2 = (const float*)d_in[11];

    float *pX, *pZ, *pH, *pF, *pK, *pQ, *pV, *pS, *pO;
    cudaGetSymbolAddress((void**)&pX, g_X);
    cudaGetSymbolAddress((void**)&pZ, g_Z);
    cudaGetSymbolAddress((void**)&pH, g_Hb);
    cudaGetSymbolAddress((void**)&pF, g_F);
    cudaGetSymbolAddress((void**)&pK, g_Kb);
    cudaGetSymbolAddress((void**)&pQ, g_Qb);
    cudaGetSymbolAddress((void**)&pV, g_Vb);
    cudaGetSymbolAddress((void**)&pS, g_S);
    cudaGetSymbolAddress((void**)&pO, g_O);

    const int nElems = NR * Dd;
    copy_kernel<<<(nElems + 255) / 256, 256>>>(x, pX, nElems);

    for (int l = 0; l < NLAYER; l++) {
        const float* W1l = W1 + (size_t)l * Dd * FFd;
        const float* b1l = b1 + (size_t)l * FFd;
        const float* W2l = W2 + (size_t)l * FFd * Dd;
        const float* b2l = b2 + (size_t)l * Dd;
        const float* Wkl = Wk + (size_t)l * Dd * Dd;
        const float* bkl = bk + (size_t)l * Dd;
        const float* Wql = Wq + (size_t)l * Dd * Dd;
        const float* bql = bq + (size_t)l * Dd;
        const float* Wvl = Wv + (size_t)l * Dd * Dd;
        const float* bvl = bv + (size_t)l * Dd;

        // FF: h = relu(x@W1+b1); f = relu(h@W2+b2)
        gemm_kernel<true><<<dim3(FFd/128, NR/128), 256>>>(pX, W1l, b1l, pH, NR, FFd, Dd);
        gemm_kernel<true><<<dim3(Dd/128,  NR/128), 256>>>(pH, W2l, b2l, pF, NR, Dd, FFd);
        // z = resnorm(x + f)
        resnorm_kernel<<<NR, 256>>>(pX, pF, pZ);
        // K,Q,V projections
        gemm_kernel<false><<<dim3(Dd/128, NR/128), 256>>>(pZ, Wkl, bkl, pK, NR, Dd, Dd);
        gemm_kernel<false><<<dim3(Dd/128, NR/128), 256>>>(pZ, Wql, bql, pQ, NR, Dd, Dd);
        gemm_kernel<false><<<dim3(Dd/128, NR/128), 256>>>(pZ, Wvl, bvl, pV, NR, Dd, Dd);
        // attention
        scores_kernel<<<dim3(Tt/64, Tt/64, Bb*Hh), 256>>>(pK, pQ, pS);
        softmax_kernel<<<Bb*Hh*Tt, 256>>>(pS);
        attnout_kernel<<<dim3(1, Tt/64, Bb*Hh), 256>>>(pS, pV, pO);
        // x = resnorm(z + attn)
        resnorm_kernel<<<NR, 256>>>(pZ, pO, pX);
    }

    copy_kernel<<<(nElems + 255) / 256, 256>>>(pX, (float*)d_out, nElems);
}

// round 2
// speedup vs baseline: 2.2956x; 2.2956x over previous
#include <cuda_runtime.h>
#include <cuda_bf16.h>
#include <math.h>
#include <stdint.h>

#define Tt   1024
#define Bb   4
#define Dd   1024
#define Hh   16
#define DH   64
#define FFd  4096
#define NR   (Tt*Bb)      // 4096 rows (row index = t*B + b)
#define LDR  (Bb*Dd)      // 4096
#define NLAYER 4

// ---------------- scratch (device globals) ---------------------------------
__device__ __align__(128) uint32_t g_Wkpk[NLAYER*Dd*Dd];
__device__ __align__(128) uint32_t g_Wqpk[NLAYER*Dd*Dd];
__device__ __align__(128) uint32_t g_Wvpk[NLAYER*Dd*Dd];
__device__ __align__(128) uint32_t g_W1pk[NLAYER*Dd*FFd];
__device__ __align__(128) uint32_t g_W2pk[NLAYER*FFd*Dd];
__device__ __align__(128) uint32_t g_Xpk[NR*Dd];
__device__ __align__(128) float    g_Xf [NR*Dd];
__device__ __align__(128) uint32_t g_Zpk[NR*Dd];
__device__ __align__(128) float    g_Zf [NR*Dd];
__device__ __align__(128) uint32_t g_Hpk[(size_t)NR*FFd];
__device__ __align__(128) float    g_Ff [NR*Dd];
__device__ __align__(128) uint32_t g_Kpk[NR*Dd];
__device__ __align__(128) uint32_t g_Qpk[NR*Dd];
__device__ __align__(128) uint32_t g_Vpk[NR*Dd];
__device__ __align__(128) float    g_Sf [(size_t)64*1024*1024];
__device__ __align__(128) uint32_t g_Apk[(size_t)64*1024*1024];
__device__ __align__(128) float    g_Of [NR*Dd];

// ---------------- helpers ---------------------------------------------------
__device__ __forceinline__ uint32_t pack_split(float x) {
    __nv_bfloat16 h = __float2bfloat16(x);
    float hf = __bfloat162float(h);
    __nv_bfloat16 l = __float2bfloat16(x - hf);
    return ((uint32_t)__bfloat16_as_ushort(h) << 16) | (uint32_t)__bfloat16_as_ushort(l);
}
__device__ __forceinline__ uint32_t prmt(uint32_t a, uint32_t b, uint32_t s) {
    uint32_t r; asm("prmt.b32 %0,%1,%2,%3;" : "=r"(r) : "r"(a), "r"(b), "r"(s)); return r;
}
__device__ __forceinline__ void ldsm4(uint32_t* r, uint32_t a) {
    asm volatile("ldmatrix.sync.aligned.m8n8.x4.shared.b16 {%0,%1,%2,%3},[%4];"
                 : "=r"(r[0]), "=r"(r[1]), "=r"(r[2]), "=r"(r[3]) : "r"(a));
}
__device__ __forceinline__ void ldsm4t(uint32_t* r, uint32_t a) {
    asm volatile("ldmatrix.sync.aligned.m8n8.x4.trans.shared.b16 {%0,%1,%2,%3},[%4];"
                 : "=r"(r[0]), "=r"(r[1]), "=r"(r[2]), "=r"(r[3]) : "r"(a));
}
__device__ __forceinline__ void mma16816(float* c, const uint32_t* a, const uint32_t* b) {
    asm volatile(
        "mma.sync.aligned.m16n8k16.row.col.f32.bf16.bf16.f32 "
        "{%0,%1,%2,%3},{%4,%5,%6,%7},{%8,%9},{%0,%1,%2,%3};"
        : "+f"(c[0]), "+f"(c[1]), "+f"(c[2]), "+f"(c[3])
        : "r"(a[0]), "r"(a[1]), "r"(a[2]), "r"(a[3]), "r"(b[0]), "r"(b[1]));
}

// ---------------- bf16x3 GEMM ----------------------------------------------
// C[m][n] = epilogue( sum_k A[m][k]*B[k][n] )
// A: packed u32 (hi,lo bf16), row-major [m][k], leading dim lda.
// B: packed u32. If BCOL: memory is B[n*ldb + k] (k contiguous per n).
//    Else: memory is B[k*ldb + n] (row-major weights).
// BATCH: 0 none; 1 scores (A=K+base, B=Q+base, C=S+z*T*T);
//        2 AV (A=probs+z*T*T, B=V+base, C=O+base).
template<int BM, int BN, int BK, int WM, int WN, bool BCOL, int BATCH,
         bool HAS_BIAS, bool RELU, bool OUTPK>
__global__ __launch_bounds__(256)
void gemm3(const uint32_t* __restrict__ Ag, const uint32_t* __restrict__ Bg,
           const float* __restrict__ bias, void* __restrict__ Cg,
           int K, int lda, int ldb, int ldc, float alpha) {
    constexpr int SA  = BK + 8;                    // b16 stride: A tiles + colmajor-B tiles
    constexpr int SB  = BN + 8;                    // b16 stride: row-major B tiles
    constexpr int BSZ = BCOL ? BN * SA : BK * SB;
    constexpr int AIT = BM * BK / 1024;
    constexpr int BIT = BK * BN / 1024;
    constexpr int MF  = WM / 16, NF = WN / 8;
    constexpr int WGN = BN / WN;

    __shared__ __align__(16) uint16_t AsH[BM * SA], AsL[BM * SA];
    __shared__ __align__(16) uint16_t BsH[BSZ],     BsL[BSZ];

    int tid = threadIdx.x, lane = tid & 31, warp = tid >> 5;
    int wm = (warp / WGN) * WM, wn = (warp % WGN) * WN;

    size_t aOff = 0, bOff = 0, cOff = 0;
    if (BATCH == 1) {
        int z = blockIdx.z; size_t base = (size_t)(z >> 4) * Dd + (size_t)(z & 15) * DH;
        aOff = base; bOff = base; cOff = (size_t)z * Tt * Tt;
    }
    if (BATCH == 2) {
        int z = blockIdx.z; size_t base = (size_t)(z >> 4) * Dd + (size_t)(z & 15) * DH;
        aOff = (size_t)z * Tt * Tt; bOff = base; cOff = base;
    }

    int m0 = blockIdx.y * BM, n0 = blockIdx.x * BN;
    const uint32_t* Ap = Ag + aOff + (size_t)m0 * lda;
    const uint32_t* Bp = BCOL ? (Bg + bOff + (size_t)n0 * ldb) : (Bg + bOff + n0);

    uint4 ra[AIT], rb[BIT];

    auto loadG = [&](int k0) {
        #pragma unroll
        for (int j = 0; j < AIT; j++) {
            int lin = tid + j * 256;
            int r = lin >> 3, kc = (lin & 7) * 4;
            ra[j] = *(const uint4*)(Ap + (size_t)r * lda + k0 + kc);
        }
        #pragma unroll
        for (int j = 0; j < BIT; j++) {
            int lin = tid + j * 256;
            if (BCOL) {
                int r = lin >> 3, kc = (lin & 7) * 4;
                rb[j] = *(const uint4*)(Bp + (size_t)r * ldb + k0 + kc);
            } else {
                constexpr int NW = BN / 4;
                int r = lin / NW, nc = (lin % NW) * 4;
                rb[j] = *(const uint4*)(Bp + (size_t)(k0 + r) * ldb + nc);
            }
        }
    };
    auto storeS = [&]() {
        #pragma unroll
        for (int j = 0; j < AIT; j++) {
            int lin = tid + j * 256;
            int r = lin >> 3, kc = (lin & 7) * 4;
            *(uint2*)&AsH[r * SA + kc] =
                make_uint2(prmt(ra[j].x, ra[j].y, 0x7632), prmt(ra[j].z, ra[j].w, 0x7632));
            *(uint2*)&AsL[r * SA + kc] =
                make_uint2(prmt(ra[j].x, ra[j].y, 0x5410), prmt(ra[j].z, ra[j].w, 0x5410));
        }
        #pragma unroll
        for (int j = 0; j < BIT; j++) {
            int lin = tid + j * 256;
            int r, c, stride;
            if (BCOL) { r = lin >> 3; c = (lin & 7) * 4; stride = SA; }
            else      { r = lin / (BN / 4); c = (lin % (BN / 4)) * 4; stride = SB; }
            *(uint2*)&BsH[r * stride + c] =
                make_uint2(prmt(rb[j].x, rb[j].y, 0x7632), prmt(rb[j].z, rb[j].w, 0x7632));
            *(uint2*)&BsL[r * stride + c] =
                make_uint2(prmt(rb[j].x, rb[j].y, 0x5410), prmt(rb[j].z, rb[j].w, 0x5410));
        }
    };

    float acc[MF][NF][4];
    #pragma unroll
    for (int i = 0; i < MF; i++)
        #pragma unroll
        for (int j = 0; j < NF; j++)
            #pragma unroll
            for (int q = 0; q < 4; q++) acc[i][j][q] = 0.f;

    uint32_t aBaseH = (uint32_t)__cvta_generic_to_shared(AsH);
    uint32_t aBaseL = (uint32_t)__cvta_generic_to_shared(AsL);
    uint32_t bBaseH = (uint32_t)__cvta_generic_to_shared(BsH);
    uint32_t bBaseL = (uint32_t)__cvta_generic_to_shared(BsL);

    loadG(0); storeS(); __syncthreads();

    for (int k0 = 0; k0 < K; k0 += BK) {
        bool more = (k0 + BK) < K;
        if (more) loadG(k0 + BK);     // LDGs in flight while we compute

        #pragma unroll
        for (int ks = 0; ks < BK; ks += 16) {
            uint32_t aH[MF][4], aL[MF][4];
            #pragma unroll
            for (int mf = 0; mf < MF; mf++) {
                int row = wm + mf * 16 + (lane & 15);
                int kc = ks + (lane >> 4) * 8;
                uint32_t off = (uint32_t)(row * SA + kc) * 2;
                ldsm4(aH[mf], aBaseH + off);
                ldsm4(aL[mf], aBaseL + off);
            }
            #pragma unroll
            for (int np = 0; np < NF; np += 2) {
                uint32_t bH[4], bL[4];
                if (BCOL) {
                    int n = wn + np * 8 + (lane & 7) + ((lane >> 4) * 8);
                    int kc = ks + ((lane >> 3) & 1) * 8;
                    uint32_t off = (uint32_t)(n * SA + kc) * 2;
                    ldsm4(bH, bBaseH + off);
                    ldsm4(bL, bBaseL + off);
                } else {
                    int k = ks + (lane & 7) + (lane & 8);
                    int n = wn + np * 8 + ((lane >> 4) * 8);
                    uint32_t off = (uint32_t)(k * SB + n) * 2;
                    ldsm4t(bH, bBaseH + off);
                    ldsm4t(bL, bBaseL + off);
                }
                #pragma unroll
                for (int mf = 0; mf < MF; mf++) {
                    #pragma unroll
                    for (int nn = 0; nn < 2; nn++) {
                        float* c = acc[mf][np + nn];
                        mma16816(c, aH[mf], bH + nn * 2);
                        mma16816(c, aH[mf], bL + nn * 2);
                        mma16816(c, aL[mf], bH + nn * 2);
                    }
                }
            }
        }
        __syncthreads();
        if (more) { storeS(); __syncthreads(); }
    }

    // epilogue
    int g = lane >> 2, t = lane & 3;
    #pragma unroll
    for (int mf = 0; mf < MF; mf++) {
        #pragma unroll
        for (int nf = 0; nf < NF; nf++) {
            int r = m0 + wm + mf * 16 + g;
            int c = n0 + wn + nf * 8 + 2 * t;
            float* a = acc[mf][nf];
            float v0 = a[0] * alpha, v1 = a[1] * alpha, v2 = a[2] * alpha, v3 = a[3] * alpha;
            if (HAS_BIAS) {
                float q0 = bias[c], q1 = bias[c + 1];
                v0 += q0; v1 += q1; v2 += q0; v3 += q1;
            }
            if (RELU) {
                v0 = fmaxf(v0, 0.f); v1 = fmaxf(v1, 0.f);
                v2 = fmaxf(v2, 0.f); v3 = fmaxf(v3, 0.f);
            }
            if (OUTPK) {
                uint32_t* C = (uint32_t*)Cg + cOff;
                *(uint2*)(C + (size_t)r * ldc + c)       = make_uint2(pack_split(v0), pack_split(v1));
                *(uint2*)(C + (size_t)(r + 8) * ldc + c) = make_uint2(pack_split(v2), pack_split(v3));
            } else {
                float* C = (float*)Cg + cOff;
                *(float2*)(C + (size_t)r * ldc + c)       = make_float2(v0, v1);
                *(float2*)(C + (size_t)(r + 8) * ldc + c) = make_float2(v2, v3);
            }
        }
    }
}

// ---------------- split kernels --------------------------------------------
__global__ void split4_kernel(const float* __restrict__ src, uint32_t* __restrict__ dst, int n4) {
    int i = blockIdx.x * blockDim.x + threadIdx.x;
    for (; i < n4; i += gridDim.x * blockDim.x) {
        float4 v = ((const float4*)src)[i];
        ((uint4*)dst)[i] = make_uint4(pack_split(v.x), pack_split(v.y),
                                      pack_split(v.z), pack_split(v.w));
    }
}
__global__ void init_split_kernel(const float* __restrict__ x, float* __restrict__ Xf,
                                  uint32_t* __restrict__ Xpk, int n4) {
    int i = blockIdx.x * blockDim.x + threadIdx.x;
    if (i < n4) {
        float4 v = ((const float4*)x)[i];
        ((float4*)Xf)[i] = v;
        ((uint4*)Xpk)[i] = make_uint4(pack_split(v.x), pack_split(v.y),
                                      pack_split(v.z), pack_split(v.w));
    }
}

// ---------------- softmax (fp32 in -> packed out) --------------------------
__global__ __launch_bounds__(256)
void softmax_split_kernel(const float* __restrict__ S, uint32_t* __restrict__ A) {
    size_t row = blockIdx.x;
    const float4* p = (const float4*)(S + row * Tt);
    uint4* o = (uint4*)(A + row * Tt);
    int tid = threadIdx.x;

    float4 v = p[tid];
    float m = fmaxf(fmaxf(v.x, v.y), fmaxf(v.z, v.w));
    #pragma unroll
    for (int d = 16; d > 0; d >>= 1) m = fmaxf(m, __shfl_xor_sync(0xffffffffu, m, d));

    __shared__ float sm[8];
    __shared__ float bmax, bsuminv;
    if ((tid & 31) == 0) sm[tid >> 5] = m;
    __syncthreads();
    if (tid == 0) {
        float mm = sm[0];
        #pragma unroll
        for (int i = 1; i < 8; i++) mm = fmaxf(mm, sm[i]);
        bmax = mm;
    }
    __syncthreads();
    m = bmax;

    v.x = expf(v.x - m); v.y = expf(v.y - m);
    v.z = expf(v.z - m); v.w = expf(v.w - m);
    float s = v.x + v.y + v.z + v.w;
    #pragma unroll
    for (int d = 16; d > 0; d >>= 1) s += __shfl_xor_sync(0xffffffffu, s, d);
    if ((tid & 31) == 0) sm[tid >> 5] = s;
    __syncthreads();
    if (tid == 0) {
        float tot = 0.f;
        #pragma unroll
        for (int i = 0; i < 8; i++) tot += sm[i];
        bsuminv = 1.f / tot;
    }
    __syncthreads();
    float inv = bsuminv;
    o[tid] = make_uint4(pack_split(v.x * inv), pack_split(v.y * inv),
                        pack_split(v.z * inv), pack_split(v.w * inv));
}

// -------- resnorm: out = ((x+fx)-mean)/(std_ddof1+eps); fp32 + packed ------
__global__ __launch_bounds__(256)
void resnorm_split_kernel(const float* __restrict__ X, const float* __restrict__ Fx,
                          float* __restrict__ Of, uint32_t* __restrict__ Opk) {
    int row = blockIdx.x;
    const float4* xp = (const float4*)(X + (size_t)row * Dd);
    const float4* fp = (const float4*)(Fx + (size_t)row * Dd);
    int tid = threadIdx.x;

    float4 x = xp[tid], f = fp[tid];
    float4 y;
    y.x = x.x + f.x; y.y = x.y + f.y; y.z = x.z + f.z; y.w = x.w + f.w;

    float s  = y.x + y.y + y.z + y.w;
    float ss = y.x * y.x + y.y * y.y + y.z * y.z + y.w * y.w;
    #pragma unroll
    for (int d = 16; d > 0; d >>= 1) {
        s  += __shfl_xor_sync(0xffffffffu, s, d);
        ss += __shfl_xor_sync(0xffffffffu, ss, d);
    }
    __shared__ float sh1[8], sh2[8];
    __shared__ float bmu, binv;
    if ((tid & 31) == 0) { sh1[tid >> 5] = s; sh2[tid >> 5] = ss; }
    __syncthreads();
    if (tid == 0) {
        float ts = 0.f, tss = 0.f;
        #pragma unroll
        for (int i = 0; i < 8; i++) { ts += sh1[i]; tss += sh2[i]; }
        float mu  = ts * (1.f / 1024.f);
        float var = (tss - 1024.f * mu * mu) * (1.f / 1023.f);
        float sd  = sqrtf(fmaxf(var, 0.f));
        bmu = mu; binv = 1.f / (sd + 1e-6f);
    }
    __syncthreads();
    float mu = bmu, inv = binv;
    float4 o;
    o.x = (y.x - mu) * inv; o.y = (y.y - mu) * inv;
    o.z = (y.z - mu) * inv; o.w = (y.w - mu) * inv;
    ((float4*)(Of + (size_t)row * Dd))[tid] = o;
    ((uint4*)(Opk + (size_t)row * Dd))[tid] =
        make_uint4(pack_split(o.x), pack_split(o.y), pack_split(o.z), pack_split(o.w));
}

__global__ void copy_kernel(const float* __restrict__ src, float* __restrict__ dst, int n) {
    int i = blockIdx.x * blockDim.x + threadIdx.x;
    if (i < n) dst[i] = src[i];
}

// ---------------------------------------------------------------------------
extern "C" void kernel_launch(void* const* d_in, const int* in_sizes, int n_in,
                              void* d_out, int out_size) {
    const float* x  = (const float*)d_in[0];
    const float* Wk = (const float*)d_in[2];
    const float* bk = (const float*)d_in[3];
    const float* Wq = (const float*)d_in[4];
    const float* bq = (const float*)d_in[5];
    const float* Wv = (const float*)d_in[6];
    const float* bv = (const float*)d_in[7];
    const float* W1 = (const float*)d_in[8];
    const float* b1 = (const float*)d_in[9];
    const float* W2 = (const float*)d_in[10];
    const float* b2 = (const float*)d_in[11];

    uint32_t *pWkpk, *pWqpk, *pWvpk, *pW1pk, *pW2pk;
    uint32_t *pXpk, *pZpk, *pHpk, *pKpk, *pQpk, *pVpk, *pApk;
    float *pXf, *pZf, *pFf, *pSf, *pOf;
    cudaGetSymbolAddress((void**)&pWkpk, g_Wkpk);
    cudaGetSymbolAddress((void**)&pWqpk, g_Wqpk);
    cudaGetSymbolAddress((void**)&pWvpk, g_Wvpk);
    cudaGetSymbolAddress((void**)&pW1pk, g_W1pk);
    cudaGetSymbolAddress((void**)&pW2pk, g_W2pk);
    cudaGetSymbolAddress((void**)&pXpk,  g_Xpk);
    cudaGetSymbolAddress((void**)&pXf,   g_Xf);
    cudaGetSymbolAddress((void**)&pZpk,  g_Zpk);
    cudaGetSymbolAddress((void**)&pZf,   g_Zf);
    cudaGetSymbolAddress((void**)&pHpk,  g_Hpk);
    cudaGetSymbolAddress((void**)&pFf,   g_Ff);
    cudaGetSymbolAddress((void**)&pKpk,  g_Kpk);
    cudaGetSymbolAddress((void**)&pQpk,  g_Qpk);
    cudaGetSymbolAddress((void**)&pVpk,  g_Vpk);
    cudaGetSymbolAddress((void**)&pSf,   g_Sf);
    cudaGetSymbolAddress((void**)&pApk,  g_Apk);
    cudaGetSymbolAddress((void**)&pOf,   g_Of);

    // split weights (every call: deterministic, ~55us)
    split4_kernel<<<4096, 256>>>(Wk, pWkpk, NLAYER * Dd * Dd / 4);
    split4_kernel<<<4096, 256>>>(Wq, pWqpk, NLAYER * Dd * Dd / 4);
    split4_kernel<<<4096, 256>>>(Wv, pWvpk, NLAYER * Dd * Dd / 4);
    split4_kernel<<<8192, 256>>>(W1, pW1pk, NLAYER * Dd * FFd / 4);
    split4_kernel<<<8192, 256>>>(W2, pW2pk, NLAYER * FFd * Dd / 4);
    init_split_kernel<<<NR * Dd / 4 / 256, 256>>>(x, pXf, pXpk, NR * Dd / 4);

    for (int l = 0; l < NLAYER; l++) {
        const uint32_t* W1l = pW1pk + (size_t)l * Dd * FFd;
        const uint32_t* W2l = pW2pk + (size_t)l * FFd * Dd;
        const uint32_t* Wkl = pWkpk + (size_t)l * Dd * Dd;
        const uint32_t* Wql = pWqpk + (size_t)l * Dd * Dd;
        const uint32_t* Wvl = pWvpk + (size_t)l * Dd * Dd;
        const float* b1l = b1 + (size_t)l * FFd;
        const float* b2l = b2 + (size_t)l * Dd;
        const float* bkl = bk + (size_t)l * Dd;
        const float* bql = bq + (size_t)l * Dd;
        const float* bvl = bv + (size_t)l * Dd;

        // FF1: Hpk = relu(Xpk @ W1 + b1), packed out
        gemm3<128,128,32,32,64,false,0,true,true,true>
            <<<dim3(FFd/128, NR/128), 256>>>(pXpk, W1l, b1l, pHpk, Dd, Dd, FFd, FFd, 1.f);
        // FF2: Ff = relu(Hpk @ W2 + b2), fp32 out
        gemm3<128,128,32,32,64,false,0,true,true,false>
            <<<dim3(Dd/128, NR/128), 256>>>(pHpk, W2l, b2l, pFf, FFd, FFd, Dd, Dd, 1.f);
        // z = resnorm(x + f)
        resnorm_split_kernel<<<NR, 256>>>(pXf, pFf, pZf, pZpk);
        // K, Q, V projections (packed out)
        gemm3<128,128,32,32,64,false,0,true,false,true>
            <<<dim3(Dd/128, NR/128), 256>>>(pZpk, Wkl, bkl, pKpk, Dd, Dd, Dd, Dd, 1.f);
        gemm3<128,128,32,32,64,false,0,true,false,true>
            <<<dim3(Dd/128, NR/128), 256>>>(pZpk, Wql, bql, pQpk, Dd, Dd, Dd, Dd, 1.f);
        gemm3<128,128,32,32,64,false,0,true,false,true>
            <<<dim3(Dd/128, NR/128), 256>>>(pZpk, Wvl, bvl, pVpk, Dd, Dd, Dd, Dd, 1.f);
        // scores: S[z][i][j] = (K_i . Q_j)/32  (batched over z = b*16+h)
        gemm3<128,128,32,32,64,true,1,false,false,false>
            <<<dim3(Tt/128, Tt/128, Bb*Hh), 256>>>(pKpk, pQpk, nullptr, pSf,
                                                   DH, LDR, LDR, Tt, 0.03125f);
        // softmax over j, packed probs out
        softmax_split_kernel<<<Bb*Hh*Tt, 256>>>(pSf, pApk);
        // AV: O[z][i][:] = sum_j A[i][j] V[j][:]
        gemm3<128,64,32,32,32,false,2,false,false,false>
            <<<dim3(1, Tt/128, Bb*Hh), 256>>>(pApk, pVpk, nullptr, pOf,
                                              Tt, Tt, LDR, LDR, 1.f);
        // x = resnorm(z + attn)
        resnorm_split_kernel<<<NR, 256>>>(pZf, pOf, pXf, pXpk);
    }

    copy_kernel<<<NR * Dd / 256, 256>>>(pXf, (float*)d_out, NR * Dd);
}